// round 2
// baseline (speedup 1.0000x reference)
#include <cuda_runtime.h>

// ---------------- problem constants ----------------
constexpr int kL   = 512;
constexpr int kB   = 32;
constexpr int kEMB = 256;
constexpr int kH   = 128;   // per-direction hidden
constexpr int kG   = 512;   // 4*kH gate rows per direction
constexpr int kN   = 1024;  // both directions' gates
constexpr int kT   = 5;
constexpr int START = 3;
constexpr int STOP  = 4;

// ---------------- scratch (device globals; no allocs allowed) ----------------
__device__ float g_x[kL * kB * kEMB];          // (l,b,e)           16.8 MB
__device__ float g_gates[kL * kB * kN];        // (l,b,[f|b] gates) 67 MB
__device__ float g_h[2 * kL * kB * kH];        // (dir,l,b,j)       16.8 MB
__device__ float g_feats[kL * kB * kT];        // (l,b,tag)

// ---------------- helpers ----------------
__device__ __forceinline__ float sigf(float x) {
    return __fdividef(1.0f, 1.0f + __expf(-x));
}
__device__ __forceinline__ float tanhfast(float x) {
    return __fdividef(2.0f, 1.0f + __expf(-2.0f * x)) - 1.0f;
}

// ---------------- K1: embedding gather ----------------
// grid = L*B blocks, 64 threads; x[l][b][:] = embed[sentence[b][l]][:]
__global__ void k_gather(const int* __restrict__ sent, const float* __restrict__ embed) {
    int lb = blockIdx.x;              // l*32 + b
    int l = lb >> 5, b = lb & 31;
    int tok = sent[b * kL + l];
    const float4* src = (const float4*)(embed + (size_t)tok * kEMB);
    float4* dst = (float4*)(g_x + (size_t)lb * kEMB);
    dst[threadIdx.x] = src[threadIdx.x];
}

// ---------------- K2: big GEMM  C = x @ [Wih_f;Wih_b]^T + bias ----------------
constexpr int BM = 128, BN = 128, BK = 8;

__global__ __launch_bounds__(256) void k_gemm(const float* __restrict__ Wf,
                                              const float* __restrict__ Wb,
                                              const float* __restrict__ biasf,
                                              const float* __restrict__ biasb) {
    __shared__ float As[BK][BM + 4];
    __shared__ float Bs[BK][BN + 4];
    const int tid = threadIdx.x;
    const int m0 = blockIdx.y * BM;
    const int n0 = blockIdx.x * BN;
    const int lr = tid >> 1;             // 0..127
    const int lc = (tid & 1) * 4;        // 0 or 4
    const int tx = tid & 15, ty = tid >> 4;

    const int nrow = n0 + lr;
    const float* Bsrc = (nrow < kG) ? (Wf + (size_t)nrow * kEMB)
                                    : (Wb + (size_t)(nrow - kG) * kEMB);
    const float* Asrc = g_x + (size_t)(m0 + lr) * kEMB;

    float acc[8][8];
#pragma unroll
    for (int i = 0; i < 8; i++)
#pragma unroll
        for (int j = 0; j < 8; j++) acc[i][j] = 0.0f;

    for (int kk = 0; kk < kEMB; kk += BK) {
        float4 a4 = *(const float4*)(Asrc + kk + lc);
        float4 b4 = *(const float4*)(Bsrc + kk + lc);
        As[lc + 0][lr] = a4.x; As[lc + 1][lr] = a4.y;
        As[lc + 2][lr] = a4.z; As[lc + 3][lr] = a4.w;
        Bs[lc + 0][lr] = b4.x; Bs[lc + 1][lr] = b4.y;
        Bs[lc + 2][lr] = b4.z; Bs[lc + 3][lr] = b4.w;
        __syncthreads();
#pragma unroll
        for (int k = 0; k < BK; k++) {
            float af[8], bf[8];
            *(float4*)(af)     = *(const float4*)(&As[k][ty * 4]);
            *(float4*)(af + 4) = *(const float4*)(&As[k][64 + ty * 4]);
            *(float4*)(bf)     = *(const float4*)(&Bs[k][tx * 4]);
            *(float4*)(bf + 4) = *(const float4*)(&Bs[k][64 + tx * 4]);
#pragma unroll
            for (int i = 0; i < 8; i++)
#pragma unroll
                for (int j = 0; j < 8; j++) acc[i][j] += af[i] * bf[j];
        }
        __syncthreads();
    }

#pragma unroll
    for (int i = 0; i < 8; i++) {
        int m = m0 + ((i < 4) ? (ty * 4 + i) : (64 + ty * 4 + i - 4));
#pragma unroll
        for (int j = 0; j < 8; j++) {
            int n = n0 + ((j < 4) ? (tx * 4 + j) : (64 + tx * 4 + j - 4));
            float bias = (n < kG) ? biasf[n] : biasb[n - kG];
            g_gates[(size_t)m * kN + n] = acc[i][j] + bias;
        }
    }
}

// ---------------- K3: LSTM recurrence ----------------
// 64 blocks: block < 32 -> forward chain batch b; block >= 32 -> backward chain.
// 512 threads, thread t owns gate row t. Whh row split: cols 0..63 in regs,
// cols 64..127 in smem laid out [colblk][t] as float4 (conflict-free).
constexpr int SW_FLOATS = 16 * 512 * 4;  // 32768 floats = 128 KB

__global__ __launch_bounds__(512, 1) void k_lstm(const float* __restrict__ Whh_f,
                                                 const float* __restrict__ Whh_b,
                                                 const float* __restrict__ h0,
                                                 const float* __restrict__ c0) {
    extern __shared__ float sm[];
    float* sw  = sm;                    // 32768 floats
    float* h_s = sm + SW_FLOATS;        // 128 floats
    float* g_s = h_s + 128;             // 512 floats

    const int t   = threadIdx.x;
    const int blk = blockIdx.x;
    const int dir = blk >> 5;
    const int b   = blk & 31;
    const float* Whh = dir ? Whh_b : Whh_f;

    // register-resident weights: cols 0..63 of row t
    float4 wreg[16];
#pragma unroll
    for (int i = 0; i < 16; i++)
        wreg[i] = *(const float4*)(Whh + (size_t)t * kH + i * 4);
    // smem weights: cols 64..127 of row t, transposed layout
#pragma unroll
    for (int i = 0; i < 16; i++) {
        float4 v = *(const float4*)(Whh + (size_t)t * kH + 64 + i * 4);
        *(float4*)(sw + ((size_t)i * 512 + t) * 4) = v;
    }

    float c = 0.0f;
    if (t < kH) {
        c = c0[(dir * kB + b) * kH + t];
        h_s[t] = h0[(dir * kB + b) * kH + t];
    }
    __syncthreads();

    int l = dir ? (kL - 1) : 0;
    const int step = dir ? -1 : 1;
    const int gofs = dir ? kG : 0;

    float pre = g_gates[((size_t)l * kB + b) * kN + gofs + t];

    for (int s = 0; s < kL; s++) {
        int ln = l + step;
        int lnc = min(max(ln, 0), kL - 1);
        float pre_next = g_gates[((size_t)lnc * kB + b) * kN + gofs + t];

        float a0 = pre, a1 = 0.0f, a2 = 0.0f, a3 = 0.0f;
        const float4* h4 = (const float4*)h_s;
#pragma unroll
        for (int i = 0; i < 16; i++) {
            float4 hv = h4[i];
            float4 wv = wreg[i];
            a0 += wv.x * hv.x; a1 += wv.y * hv.y;
            a2 += wv.z * hv.z; a3 += wv.w * hv.w;
        }
#pragma unroll
        for (int i = 0; i < 16; i++) {
            float4 hv = h4[16 + i];
            float4 wv = *(const float4*)(sw + ((size_t)i * 512 + t) * 4);
            a0 += wv.x * hv.x; a1 += wv.y * hv.y;
            a2 += wv.z * hv.z; a3 += wv.w * hv.w;
        }
        g_s[t] = (a0 + a1) + (a2 + a3);
        __syncthreads();

        if (t < kH) {
            float gi = g_s[t];
            float gf = g_s[kH + t];
            float gg = g_s[2 * kH + t];
            float go = g_s[3 * kH + t];
            c = sigf(gf) * c + sigf(gi) * tanhfast(gg);
            float h = sigf(go) * tanhfast(c);
            h_s[t] = h;
            g_h[(((size_t)dir * kL + l) * kB + b) * kH + t] = h;
        }
        __syncthreads();

        pre = pre_next;
        l = ln;
    }
}

// ---------------- K4: feats = concat(hf,hb) @ W_tag^T + b_tag ----------------
// one warp per (l,b); 8 warps per block
__global__ void k_feats(const float* __restrict__ Wt, const float* __restrict__ bt) {
    int lb = blockIdx.x * 8 + (threadIdx.x >> 5);
    int lane = threadIdx.x & 31;
    const float4* hbase = (const float4*)g_h;
    float4 a = hbase[(size_t)lb * 32 + lane];                        // dir 0
    float4 cc = hbase[(size_t)kL * kB * 32 + (size_t)lb * 32 + lane]; // dir 1
#pragma unroll
    for (int tag = 0; tag < kT; tag++) {
        float4 w0 = *(const float4*)(Wt + tag * 2 * kH + lane * 4);
        float4 w1 = *(const float4*)(Wt + tag * 2 * kH + kH + lane * 4);
        float p = a.x * w0.x + a.y * w0.y + a.z * w0.z + a.w * w0.w
                + cc.x * w1.x + cc.y * w1.y + cc.z * w1.z + cc.w * w1.w;
        p += __shfl_xor_sync(0xffffffffu, p, 16);
        p += __shfl_xor_sync(0xffffffffu, p, 8);
        p += __shfl_xor_sync(0xffffffffu, p, 4);
        p += __shfl_xor_sync(0xffffffffu, p, 2);
        p += __shfl_xor_sync(0xffffffffu, p, 1);
        if (lane == 0) g_feats[(size_t)lb * kT + tag] = p + bt[tag];
    }
}

// ---------------- K5: CRF forward scan + gold score + final scalar ----------------
// 512 threads. warps 0..7: CRF (4 batches/warp, 5 active lanes per batch,
// shuffle-only groups of 8 lanes). warps 8..15: gold score (4 batches/warp,
// 8 lanes per batch).
__global__ __launch_bounds__(512) void k_crf(const int* __restrict__ tags,
                                             const int* __restrict__ mask,
                                             const float* __restrict__ tr,
                                             float* __restrict__ out) {
    __shared__ float fwd_s[kB];
    __shared__ float gold_s[kB];
    const int tid = threadIdx.x;
    const int w = tid >> 5, lane = tid & 31;

    if (w < 8) {
        const int bi = lane >> 3;       // 0..3
        const int i  = lane & 7;        // tag id (valid if < 5)
        const int b  = w * 4 + bi;
        const int ie = (i < kT) ? i : (kT - 1);
        const int base = lane & 24;     // bi*8

        float tr0 = tr[ie * kT + 0], tr1 = tr[ie * kT + 1], tr2 = tr[ie * kT + 2];
        float tr3 = tr[ie * kT + 3], tr4 = tr[ie * kT + 4];
        float alpha = (i == START) ? 0.0f : -10000.0f;
        const int mb = mask[b];
        float amask = 0.0f;

        for (int l = 1; l <= kL - 2; l++) {
            float f = g_feats[((size_t)l * kB + b) * kT + ie];
            float a0 = __shfl_sync(0xffffffffu, alpha, base + 0);
            float a1 = __shfl_sync(0xffffffffu, alpha, base + 1);
            float a2 = __shfl_sync(0xffffffffu, alpha, base + 2);
            float a3 = __shfl_sync(0xffffffffu, alpha, base + 3);
            float a4 = __shfl_sync(0xffffffffu, alpha, base + 4);
            float v0 = a0 + tr0, v1 = a1 + tr1, v2 = a2 + tr2;
            float v3 = a3 + tr3, v4 = a4 + tr4;
            float m = fmaxf(fmaxf(fmaxf(v0, v1), fmaxf(v2, v3)), v4);
            float ssum = __expf(v0 - m) + __expf(v1 - m) + __expf(v2 - m)
                       + __expf(v3 - m) + __expf(v4 - m);
            alpha = f + m + __logf(ssum);
            if (l == mb) amask = alpha;
        }
        // terminal logsumexp of amask + trans[STOP][:]
        float t0 = __shfl_sync(0xffffffffu, amask, base + 0) + tr[STOP * kT + 0];
        float t1 = __shfl_sync(0xffffffffu, amask, base + 1) + tr[STOP * kT + 1];
        float t2 = __shfl_sync(0xffffffffu, amask, base + 2) + tr[STOP * kT + 2];
        float t3 = __shfl_sync(0xffffffffu, amask, base + 3) + tr[STOP * kT + 3];
        float t4 = __shfl_sync(0xffffffffu, amask, base + 4) + tr[STOP * kT + 4];
        float m = fmaxf(fmaxf(fmaxf(t0, t1), fmaxf(t2, t3)), t4);
        float ssum = __expf(t0 - m) + __expf(t1 - m) + __expf(t2 - m)
                   + __expf(t3 - m) + __expf(t4 - m);
        if (i == 0) fwd_s[b] = m + __logf(ssum);
    } else if (w < 16) {
        const int b = (w - 8) * 4 + (lane >> 3);
        const int lp = lane & 7;
        const int mb = mask[b];
        float s = 0.0f;
        for (int p = lp; p < mb; p += 8) {
            int tp = tags[b * kL + p];
            int tn = tags[b * kL + p + 1];
            s += tr[tn * kT + tp] + g_feats[((size_t)(p + 1) * kB + b) * kT + tn];
        }
        s += __shfl_xor_sync(0xffffffffu, s, 4);
        s += __shfl_xor_sync(0xffffffffu, s, 2);
        s += __shfl_xor_sync(0xffffffffu, s, 1);
        if (lp == 0) gold_s[b] = s + tr[STOP * kT + tags[b * kL + mb]];
    }
    __syncthreads();
    if (tid == 0) {
        float fs = 0.0f, gs = 0.0f;
        for (int bb = 0; bb < kB; bb++) { fs += fwd_s[bb]; gs += gold_s[bb]; }
        out[0] = (fs - gs) * (1.0f / kB);
    }
}

// ---------------- launch ----------------
extern "C" void kernel_launch(void* const* d_in, const int* in_sizes, int n_in,
                              void* d_out, int out_size) {
    const int*   sentence = (const int*)d_in[0];
    const int*   tags     = (const int*)d_in[1];
    const int*   mask     = (const int*)d_in[2];
    const float* embed    = (const float*)d_in[3];
    const float* Wih_f    = (const float*)d_in[4];
    const float* Whh_f    = (const float*)d_in[5];
    const float* b_f      = (const float*)d_in[6];
    const float* Wih_b    = (const float*)d_in[7];
    const float* Whh_b    = (const float*)d_in[8];
    const float* b_b      = (const float*)d_in[9];
    const float* W_tag    = (const float*)d_in[10];
    const float* b_tag    = (const float*)d_in[11];
    const float* trans    = (const float*)d_in[12];
    const float* h0       = (const float*)d_in[13];
    const float* c0       = (const float*)d_in[14];
    (void)in_sizes; (void)n_in; (void)out_size;

    // dynamic smem for the recurrence kernel (134 KB > 48 KB default)
    const int lstm_smem = (SW_FLOATS + 128 + 512) * (int)sizeof(float);
    cudaFuncSetAttribute(k_lstm, cudaFuncAttributeMaxDynamicSharedMemorySize, lstm_smem);

    k_gather<<<kL * kB, 64>>>(sentence, embed);

    dim3 gg(kN / BN, (kL * kB) / BM);
    k_gemm<<<gg, 256>>>(Wih_f, Wih_b, b_f, b_b);

    k_lstm<<<64, 512, lstm_smem>>>(Whh_f, Whh_b, h0, c0);

    k_feats<<<(kL * kB) / 8, 256>>>(W_tag, b_tag);

    k_crf<<<1, 512>>>(tags, mask, trans, (float*)d_out);
}

// round 4
// speedup vs baseline: 1.2626x; 1.2626x over previous
#include <cuda_runtime.h>
#include <cuda_bf16.h>
#include <cstdint>

// ---------------- problem constants ----------------
constexpr int kL   = 512;
constexpr int kB   = 32;
constexpr int kEMB = 256;
constexpr int kH   = 128;   // per-direction hidden
constexpr int kG   = 512;   // 4*kH gate rows per direction
constexpr int kN   = 1024;  // both directions' gates
constexpr int kT   = 5;
constexpr int START = 3;
constexpr int STOP  = 4;

// ---------------- scratch (device globals; no allocs allowed) ----------------
__device__ __nv_bfloat16 g_xh[kL * kB * kEMB];   // x hi (bf16)
__device__ __nv_bfloat16 g_xl[kL * kB * kEMB];   // x lo (bf16 residual)
__device__ __nv_bfloat16 g_wh[kN * kEMB];        // [Wih_f;Wih_b] hi
__device__ __nv_bfloat16 g_wl[kN * kEMB];        // [Wih_f;Wih_b] lo
__device__ float g_gates[kL * kB * kN];          // (l,b,[fwd|bwd] gates)
__device__ float g_h[2 * kL * kB * kH];          // (dir,l,b,j)
__device__ float g_feats[kL * kB * kT];          // (l,b,tag)

// ---------------- small helpers ----------------
__device__ __forceinline__ float sigf(float x) {
    return __fdividef(1.0f, 1.0f + __expf(-x));
}
__device__ __forceinline__ float tanhfast(float x) {
    return __fdividef(2.0f, 1.0f + __expf(-2.0f * x)) - 1.0f;
}
__device__ __forceinline__ uint32_t smem_u32(const void* p) {
    uint32_t a;
    asm("{ .reg .u64 t; cvta.to.shared.u64 t, %1; cvt.u32.u64 %0, t; }" : "=r"(a) : "l"(p));
    return a;
}
__device__ __forceinline__ uint32_t swz128(uint32_t off) {
    return off ^ ((off >> 3) & 0x70);
}
__device__ __forceinline__ void cpasync16(uint32_t dst, const void* src) {
    asm volatile("cp.async.cg.shared.global [%0], [%1], 16;" :: "r"(dst), "l"(src));
}
__device__ __forceinline__ void ldsm4(uint32_t* r, uint32_t addr) {
    asm volatile("ldmatrix.sync.aligned.m8n8.x4.shared.b16 {%0,%1,%2,%3}, [%4];"
                 : "=r"(r[0]), "=r"(r[1]), "=r"(r[2]), "=r"(r[3]) : "r"(addr));
}
__device__ __forceinline__ void mma16816(float* d, const uint32_t* a, uint32_t b0, uint32_t b1) {
    asm volatile("mma.sync.aligned.m16n8k16.row.col.f32.bf16.bf16.f32 "
                 "{%0,%1,%2,%3}, {%4,%5,%6,%7}, {%8,%9}, {%0,%1,%2,%3};"
                 : "+f"(d[0]), "+f"(d[1]), "+f"(d[2]), "+f"(d[3])
                 : "r"(a[0]), "r"(a[1]), "r"(a[2]), "r"(a[3]), "r"(b0), "r"(b1));
}
// packed fp32x2 FMA (Blackwell dual fp32 path)
__device__ __forceinline__ void ffma2(unsigned long long& d, unsigned long long a,
                                      unsigned long long b) {
    asm("fma.rn.f32x2 %0, %1, %2, %3;" : "=l"(d) : "l"(a), "l"(b), "l"(d));
}
__device__ __forceinline__ unsigned long long pack2(float lo, float hi) {
    unsigned long long r;
    asm("mov.b64 %0, {%1, %2};" : "=l"(r) : "f"(lo), "f"(hi));
    return r;
}
__device__ __forceinline__ float2 unpack2(unsigned long long v) {
    float lo, hi;
    asm("mov.b64 {%0, %1}, %2;" : "=f"(lo), "=f"(hi) : "l"(v));
    return make_float2(lo, hi);
}

// ---------------- K1: embedding gather + bf16 hi/lo split ----------------
__global__ void k_gather(const int* __restrict__ sent, const float* __restrict__ embed) {
    int lb = blockIdx.x;              // l*32 + b
    int l = lb >> 5, b = lb & 31;
    int tok = sent[b * kL + l];
    float4 v = ((const float4*)(embed + (size_t)tok * kEMB))[threadIdx.x];
    float xs[4] = {v.x, v.y, v.z, v.w};
    ushort4 hp, lp;
    unsigned short* hpp = (unsigned short*)&hp;
    unsigned short* lpp = (unsigned short*)&lp;
#pragma unroll
    for (int i = 0; i < 4; i++) {
        __nv_bfloat16 h = __float2bfloat16_rn(xs[i]);
        __nv_bfloat16 lo = __float2bfloat16_rn(xs[i] - __bfloat162float(h));
        hpp[i] = *(unsigned short*)&h;
        lpp[i] = *(unsigned short*)&lo;
    }
    size_t o = (size_t)lb * kEMB + threadIdx.x * 4;
    *(ushort4*)(g_xh + o) = hp;
    *(ushort4*)(g_xl + o) = lp;
}

// ---------------- K1b: weight bf16 hi/lo split ----------------
__global__ void k_wconv(const float* __restrict__ Wf, const float* __restrict__ Wb) {
    int row = blockIdx.x;             // 0..1023
    int k = threadIdx.x;              // 0..255
    float v = (row < kG) ? Wf[(size_t)row * kEMB + k] : Wb[(size_t)(row - kG) * kEMB + k];
    __nv_bfloat16 h = __float2bfloat16_rn(v);
    __nv_bfloat16 lo = __float2bfloat16_rn(v - __bfloat162float(h));
    g_wh[(size_t)row * kEMB + k] = h;
    g_wl[(size_t)row * kEMB + k] = lo;
}

// ---------------- K2: mma.sync bf16 GEMM  g_gates = x @ W^T + bias ----------------
// Effective K = 768 = 3 segments of 256: (xh,wh), (xh,wl), (xl,wh).
// Block tile 128x128, K-chunk 64, double-buffered cp.async, SW128 swizzle.
// 8 warps: warp (wid&1) -> 64-row M slot, (wid>>2? no: wid>>1) -> 32-col N slot.
constexpr int GKC = 64;                 // K per chunk (bf16)
constexpr int NCHUNK = 12;              // 768 / 64
constexpr int GBUF = 32768;             // A(16KB)+B(16KB) per buffer
constexpr int GEMM_SMEM = 2 * GBUF;     // 64 KB

__device__ __forceinline__ void ld_chunk(uint32_t sbase, int ck, int buf, int m0, int n0) {
    const int tid = threadIdx.x;
    const int seg = ck >> 2;
    const int koff = (ck & 3) * GKC;
    const __nv_bfloat16* Ag = (seg < 2) ? g_xh : g_xl;
    const __nv_bfloat16* Bg = (seg == 1) ? g_wl : g_wh;
    const uint32_t abase = sbase + buf * GBUF;
    const uint32_t bbase = abase + 16384;
#pragma unroll
    for (int i = 0; i < 4; i++) {
        int idx = i * 256 + tid;        // 0..1023 : 128 rows x 8 16B-chunks
        int r = idx >> 3;
        int c8 = idx & 7;               // 16B chunk within 128B row
        uint32_t so = swz128((uint32_t)(r * 128 + c8 * 16));
        cpasync16(abase + so, Ag + (size_t)(m0 + r) * kEMB + koff + c8 * 8);
        cpasync16(bbase + so, Bg + (size_t)(n0 + r) * kEMB + koff + c8 * 8);
    }
}

__global__ __launch_bounds__(256, 2) void k_gemm_mma(const float* __restrict__ biasf,
                                                     const float* __restrict__ biasb) {
    extern __shared__ __align__(1024) char smem[];
    const uint32_t sbase = smem_u32(smem);
    const int tid = threadIdx.x;
    const int wid = tid >> 5;
    const int lane = tid & 31;
    const int m0 = blockIdx.y * 128;
    const int n0 = blockIdx.x * 128;
    const int wm = (wid & 1) * 64;      // warp M offset in tile
    const int wn = (wid >> 1) * 32;     // warp N offset in tile

    float acc[4][4][4];
#pragma unroll
    for (int a = 0; a < 4; a++)
#pragma unroll
        for (int b = 0; b < 4; b++)
#pragma unroll
            for (int c = 0; c < 4; c++) acc[a][b][c] = 0.0f;

    ld_chunk(sbase, 0, 0, m0, n0);
    asm volatile("cp.async.commit_group;");

    const int rbase = (lane & 7) + ((lane >> 3) & 1) * 8;
    const int cext = (lane >> 4) * 16;

    for (int ck = 0; ck < NCHUNK; ck++) {
        if (ck + 1 < NCHUNK) ld_chunk(sbase, ck + 1, (ck + 1) & 1, m0, n0);
        asm volatile("cp.async.commit_group;");
        asm volatile("cp.async.wait_group 1;");
        __syncthreads();

        const uint32_t abuf = sbase + (ck & 1) * GBUF;
        const uint32_t bbuf = abuf + 16384;
#pragma unroll
        for (int k16 = 0; k16 < 4; k16++) {
            const int cb = k16 * 32 + cext;
            uint32_t a[4][4];
#pragma unroll
            for (int mi = 0; mi < 4; mi++)
                ldsm4(a[mi], abuf + swz128((uint32_t)((wm + mi * 16 + rbase) * 128 + cb)));
            uint32_t bfr[2][4];
#pragma unroll
            for (int p = 0; p < 2; p++)
                ldsm4(bfr[p], bbuf + swz128((uint32_t)((wn + p * 16 + rbase) * 128 + cb)));
#pragma unroll
            for (int mi = 0; mi < 4; mi++)
#pragma unroll
                for (int nj = 0; nj < 4; nj++)
                    mma16816(acc[mi][nj], a[mi], bfr[nj >> 1][nj & 1], bfr[nj >> 1][(nj & 1) + 2]);
        }
        __syncthreads();
    }

    // epilogue + bias
#pragma unroll
    for (int mi = 0; mi < 4; mi++) {
        int row = m0 + wm + mi * 16 + (lane >> 2);
#pragma unroll
        for (int nj = 0; nj < 4; nj++) {
            int col = n0 + wn + nj * 8 + (lane & 3) * 2;
            float bx = (col < kG) ? biasf[col] : biasb[col - kG];
            float by = (col + 1 < kG) ? biasf[col + 1] : biasb[col + 1 - kG];
            float2 v0 = make_float2(acc[mi][nj][0] + bx, acc[mi][nj][1] + by);
            float2 v1 = make_float2(acc[mi][nj][2] + bx, acc[mi][nj][3] + by);
            *(float2*)(g_gates + (size_t)row * kN + col) = v0;
            *(float2*)(g_gates + (size_t)(row + 8) * kN + col) = v1;
        }
    }
}

// ---------------- K3: LSTM recurrence (fp32x2 packed FMA) ----------------
// 64 blocks (chain = dir*32+b), 512 threads, thread t owns gate row t.
// Whh row split: cols 0..79 in registers, cols 80..127 in smem (spread layout).
constexpr int WREG4 = 20;                    // float4 groups in registers
constexpr int WSM4  = 12;                    // float4 groups in smem
constexpr int SW_FLOATS = WSM4 * 512 * 4;    // 24576 floats = 96 KB

__global__ __launch_bounds__(512, 1) void k_lstm(const float* __restrict__ Whh_f,
                                                 const float* __restrict__ Whh_b,
                                                 const float* __restrict__ h0,
                                                 const float* __restrict__ c0) {
    extern __shared__ float sm[];
    float* sw  = sm;                    // spread weights
    float* h_s = sm + SW_FLOATS;        // 128 floats
    float* g_s = h_s + 128;             // 512 floats

    const int t   = threadIdx.x;
    const int blk = blockIdx.x;
    const int dir = blk >> 5;
    const int b   = blk & 31;
    const float* Whh = dir ? Whh_b : Whh_f;

    ulonglong2 wp[WREG4];
#pragma unroll
    for (int i = 0; i < WREG4; i++)
        wp[i] = *(const ulonglong2*)(Whh + (size_t)t * kH + i * 4);
#pragma unroll
    for (int i = 0; i < WSM4; i++) {
        float4 v = *(const float4*)(Whh + (size_t)t * kH + WREG4 * 4 + i * 4);
        *(float4*)(sw + ((size_t)i * 512 + t) * 4) = v;
    }

    float c = 0.0f;
    if (t < kH) {
        c = c0[(dir * kB + b) * kH + t];
        h_s[t] = h0[(dir * kB + b) * kH + t];
    }
    __syncthreads();

    int l = dir ? (kL - 1) : 0;
    const int step = dir ? -1 : 1;
    const int gofs = dir ? kG : 0;

    float pre = g_gates[((size_t)l * kB + b) * kN + gofs + t];

    for (int s = 0; s < kL; s++) {
        int ln = l + step;
        int lnc = min(max(ln, 0), kL - 1);
        float pre_next = g_gates[((size_t)lnc * kB + b) * kN + gofs + t];

        unsigned long long acc01 = pack2(pre, 0.0f);
        unsigned long long acc23 = 0ULL;
        const ulonglong2* h2 = (const ulonglong2*)h_s;
#pragma unroll
        for (int i = 0; i < WREG4; i++) {
            ulonglong2 hv = h2[i];
            ffma2(acc01, wp[i].x, hv.x);
            ffma2(acc23, wp[i].y, hv.y);
        }
#pragma unroll
        for (int i = 0; i < WSM4; i++) {
            ulonglong2 hv = h2[WREG4 + i];
            ulonglong2 wv = *(const ulonglong2*)(sw + ((size_t)i * 512 + t) * 4);
            ffma2(acc01, wv.x, hv.x);
            ffma2(acc23, wv.y, hv.y);
        }
        float2 p01 = unpack2(acc01);
        float2 p23 = unpack2(acc23);
        g_s[t] = (p01.x + p01.y) + (p23.x + p23.y);
        __syncthreads();

        if (t < kH) {
            float gi = g_s[t];
            float gf = g_s[kH + t];
            float gg = g_s[2 * kH + t];
            float go = g_s[3 * kH + t];
            c = sigf(gf) * c + sigf(gi) * tanhfast(gg);
            float h = sigf(go) * tanhfast(c);
            h_s[t] = h;
            g_h[(((size_t)dir * kL + l) * kB + b) * kH + t] = h;
        }
        __syncthreads();

        pre = pre_next;
        l = ln;
    }
}

// ---------------- K4: feats = concat(hf,hb) @ W_tag^T + b_tag ----------------
__global__ void k_feats(const float* __restrict__ Wt, const float* __restrict__ bt) {
    int lb = blockIdx.x * 8 + (threadIdx.x >> 5);
    int lane = threadIdx.x & 31;
    const float4* hbase = (const float4*)g_h;
    float4 a = hbase[(size_t)lb * 32 + lane];
    float4 cc = hbase[(size_t)kL * kB * 32 + (size_t)lb * 32 + lane];
#pragma unroll
    for (int tag = 0; tag < kT; tag++) {
        float4 w0 = *(const float4*)(Wt + tag * 2 * kH + lane * 4);
        float4 w1 = *(const float4*)(Wt + tag * 2 * kH + kH + lane * 4);
        float p = a.x * w0.x + a.y * w0.y + a.z * w0.z + a.w * w0.w
                + cc.x * w1.x + cc.y * w1.y + cc.z * w1.z + cc.w * w1.w;
        p += __shfl_xor_sync(0xffffffffu, p, 16);
        p += __shfl_xor_sync(0xffffffffu, p, 8);
        p += __shfl_xor_sync(0xffffffffu, p, 4);
        p += __shfl_xor_sync(0xffffffffu, p, 2);
        p += __shfl_xor_sync(0xffffffffu, p, 1);
        if (lane == 0) g_feats[(size_t)lb * kT + tag] = p + bt[tag];
    }
}

// ---------------- K5: CRF forward scan + gold score ----------------
__global__ __launch_bounds__(512) void k_crf(const int* __restrict__ tags,
                                             const int* __restrict__ mask,
                                             const float* __restrict__ tr,
                                             float* __restrict__ out) {
    __shared__ float fwd_s[kB];
    __shared__ float gold_s[kB];
    const int tid = threadIdx.x;
    const int w = tid >> 5, lane = tid & 31;

    if (w < 8) {
        const int bi = lane >> 3;
        const int i  = lane & 7;
        const int b  = w * 4 + bi;
        const int ie = (i < kT) ? i : (kT - 1);
        const int base = lane & 24;

        float tr0 = tr[ie * kT + 0], tr1 = tr[ie * kT + 1], tr2 = tr[ie * kT + 2];
        float tr3 = tr[ie * kT + 3], tr4 = tr[ie * kT + 4];
        float alpha = (i == START) ? 0.0f : -10000.0f;
        const int mb = mask[b];
        float amask = 0.0f;

        for (int l = 1; l <= kL - 2; l++) {
            float f = g_feats[((size_t)l * kB + b) * kT + ie];
            float a0 = __shfl_sync(0xffffffffu, alpha, base + 0);
            float a1 = __shfl_sync(0xffffffffu, alpha, base + 1);
            float a2 = __shfl_sync(0xffffffffu, alpha, base + 2);
            float a3 = __shfl_sync(0xffffffffu, alpha, base + 3);
            float a4 = __shfl_sync(0xffffffffu, alpha, base + 4);
            float v0 = a0 + tr0, v1 = a1 + tr1, v2 = a2 + tr2;
            float v3 = a3 + tr3, v4 = a4 + tr4;
            float m = fmaxf(fmaxf(fmaxf(v0, v1), fmaxf(v2, v3)), v4);
            float ssum = __expf(v0 - m) + __expf(v1 - m) + __expf(v2 - m)
                       + __expf(v3 - m) + __expf(v4 - m);
            alpha = f + m + __logf(ssum);
            if (l == mb) amask = alpha;
        }
        float t0 = __shfl_sync(0xffffffffu, amask, base + 0) + tr[STOP * kT + 0];
        float t1 = __shfl_sync(0xffffffffu, amask, base + 1) + tr[STOP * kT + 1];
        float t2 = __shfl_sync(0xffffffffu, amask, base + 2) + tr[STOP * kT + 2];
        float t3 = __shfl_sync(0xffffffffu, amask, base + 3) + tr[STOP * kT + 3];
        float t4 = __shfl_sync(0xffffffffu, amask, base + 4) + tr[STOP * kT + 4];
        float m = fmaxf(fmaxf(fmaxf(t0, t1), fmaxf(t2, t3)), t4);
        float ssum = __expf(t0 - m) + __expf(t1 - m) + __expf(t2 - m)
                   + __expf(t3 - m) + __expf(t4 - m);
        if (i == 0) fwd_s[b] = m + __logf(ssum);
    } else if (w < 16) {
        const int b = (w - 8) * 4 + (lane >> 3);
        const int lp = lane & 7;
        const int mb = mask[b];
        float s = 0.0f;
        for (int p = lp; p < mb; p += 8) {
            int tp = tags[b * kL + p];
            int tn = tags[b * kL + p + 1];
            s += tr[tn * kT + tp] + g_feats[((size_t)(p + 1) * kB + b) * kT + tn];
        }
        s += __shfl_xor_sync(0xffffffffu, s, 4);
        s += __shfl_xor_sync(0xffffffffu, s, 2);
        s += __shfl_xor_sync(0xffffffffu, s, 1);
        if (lp == 0) gold_s[b] = s + tr[STOP * kT + tags[b * kL + mb]];
    }
    __syncthreads();
    if (tid == 0) {
        float fs = 0.0f, gs = 0.0f;
        for (int bb = 0; bb < kB; bb++) { fs += fwd_s[bb]; gs += gold_s[bb]; }
        out[0] = (fs - gs) * (1.0f / kB);
    }
}

// ---------------- launch ----------------
extern "C" void kernel_launch(void* const* d_in, const int* in_sizes, int n_in,
                              void* d_out, int out_size) {
    const int*   sentence = (const int*)d_in[0];
    const int*   tags     = (const int*)d_in[1];
    const int*   mask     = (const int*)d_in[2];
    const float* embed    = (const float*)d_in[3];
    const float* Wih_f    = (const float*)d_in[4];
    const float* Whh_f    = (const float*)d_in[5];
    const float* b_f      = (const float*)d_in[6];
    const float* Wih_b    = (const float*)d_in[7];
    const float* Whh_b    = (const float*)d_in[8];
    const float* b_b      = (const float*)d_in[9];
    const float* W_tag    = (const float*)d_in[10];
    const float* b_tag    = (const float*)d_in[11];
    const float* trans    = (const float*)d_in[12];
    const float* h0       = (const float*)d_in[13];
    const float* c0       = (const float*)d_in[14];
    (void)in_sizes; (void)n_in; (void)out_size;

    const int lstm_smem = (SW_FLOATS + 128 + 512) * (int)sizeof(float);
    cudaFuncSetAttribute(k_lstm, cudaFuncAttributeMaxDynamicSharedMemorySize, lstm_smem);
    cudaFuncSetAttribute(k_gemm_mma, cudaFuncAttributeMaxDynamicSharedMemorySize, GEMM_SMEM);

    k_gather<<<kL * kB, 64>>>(sentence, embed);
    k_wconv<<<kN, kEMB>>>(Wih_f, Wih_b);

    dim3 gg(kN / 128, (kL * kB) / 128);   // (8, 128)
    k_gemm_mma<<<gg, 256, GEMM_SMEM>>>(b_f, b_b);

    k_lstm<<<64, 512, lstm_smem>>>(Whh_f, Whh_b, h0, c0);

    k_feats<<<(kL * kB) / 8, 256>>>(W_tag, b_tag);

    k_crf<<<1, 512>>>(tags, mask, trans, (float*)d_out);
}